// round 16
// baseline (speedup 1.0000x reference)
#include <cuda_runtime.h>
#include <cuda_fp16.h>
#include <math.h>
#include <stdint.h>

#define BSZ    2048
#define LATENT 128
#define CCLS   8
#define HID    1024
#define DD     512
#define NMAXX  4096
#define NTG    128
#define NT     256

__constant__ int c_counts[CCLS] = {1024, 1536, 2048, 2560, 3072, 3584, 3840, 4096};

// fp16 operand buffers
__device__ __align__(16) __half g_z16[BSZ * LATENT];
__device__ __align__(16) __half g_W1T[HID * LATENT];          // [n][k]
__device__ __align__(16) __half g_h16[BSZ * HID];
__device__ __align__(16) __half g_W2T[HID * HID];             // [n][k]
__device__ __align__(16) __half g_t16[BSZ * HID];
__device__ __align__(16) __half g_WaT[(size_t)CCLS * NMAXX * HID];   // [c][n][k]
__device__ __align__(16) __half g_beta16[(size_t)BSZ * NMAXX];       // beta * 256
__device__ __align__(16) __half g_XbT[(size_t)CCLS * DD * NMAXX];    // [c][d][n]
__device__ __align__(16) __half g_lpart16[2][(size_t)BSZ * NMAXX];
// fp32 partials / reductions
__device__ __align__(16) float g_part[4][BSZ * HID];
__device__ __align__(16) float g_opart[4][BSZ * DD];
__device__ __align__(16) float g_cmpart[CCLS * 64 * DD];
__device__ __align__(16) float g_colmean[CCLS * DD];
__device__ int g_order[BSZ];
__device__ int g_class_off[CCLS + 1];

__device__ __forceinline__ float gelu_exact(float x) {
    return 0.5f * x * (1.0f + erff(x * 0.70710678118654752f));
}

__device__ __forceinline__ float exp_poly(float x) {
    float p = fmaf(x, 1.984126984e-4f, 1.388888889e-3f);
    p = fmaf(x, p, 8.333333333e-3f);
    p = fmaf(x, p, 4.166666667e-2f);
    p = fmaf(x, p, 1.666666667e-1f);
    p = fmaf(x, p, 0.5f);
    p = fmaf(x, p, 1.0f);
    p = fmaf(x, p, 1.0f);
    return p;
}

__device__ __forceinline__ void mma16(float* d, const uint32_t* a, const uint32_t* b) {
    asm volatile(
        "mma.sync.aligned.m16n8k16.row.col.f32.f16.f16.f32 "
        "{%0,%1,%2,%3},{%4,%5,%6,%7},{%8,%9},{%0,%1,%2,%3};\n"
        : "+f"(d[0]), "+f"(d[1]), "+f"(d[2]), "+f"(d[3])
        : "r"(a[0]), "r"(a[1]), "r"(a[2]), "r"(a[3]), "r"(b[0]), "r"(b[1]));
}

#define LDSM4(r0, r1, r2, r3, addr) \
    asm volatile("ldmatrix.sync.aligned.m8n8.x4.shared.b16 {%0,%1,%2,%3}, [%4];" \
        : "=r"(r0), "=r"(r1), "=r"(r2), "=r"(r3) : "r"(addr))

__device__ __forceinline__ void cpa16(uint32_t dst, const void* src, bool pred) {
    int sz = pred ? 16 : 0;  // sz=0 -> zero-fill (deterministic)
    asm volatile("cp.async.cg.shared.global [%0], [%1], 16, %2;\n"
                 :: "r"(dst), "l"(src), "r"(sz));
}
#define CP_COMMIT asm volatile("cp.async.commit_group;\n")
#define CP_WAIT1  asm volatile("cp.async.wait_group 1;\n")

// Stage: rows of 128B (K=64 halves), SW128 swizzle -> conflict-free STS + LDSM.
#define SWB(o) ((uint32_t)(o) ^ ((((uint32_t)(o)) >> 3) & 0x70))
#define ASTG_S 8192
#define BSTG   16384
#define ASTG_L 16384

// ================= S config: 64(M) x 128(N), 128 thr, warp 32x64 ===========
#define G16_PROLOG_S \
    __shared__ __align__(128) uint8_t As[2][ASTG_S]; \
    __shared__ __align__(128) uint8_t Bs[2][BSTG]; \
    int tid = threadIdx.x; int lane = tid & 31; int wid = tid >> 5; \
    int wm = (wid & 1) * 32, wn = (wid >> 1) * 64; \
    int g = lane >> 2, tg = lane & 3; \
    float acc[2][8][4] = {}; \
    uint32_t aBase = (uint32_t)__cvta_generic_to_shared(&As[0][0]); \
    uint32_t bBase = (uint32_t)__cvta_generic_to_shared(&Bs[0][0]); \
    int ar = tid >> 1, ah = tid & 1; \
    uint32_t aoffs[4]; \
    { uint32_t abl = (uint32_t)(ar * 128 + ah * 64); uint32_t axm = (uint32_t)((ar & 7) << 4); \
      aoffs[0] = (abl) ^ axm; aoffs[1] = (abl + 16) ^ axm; \
      aoffs[2] = (abl + 32) ^ axm; aoffs[3] = (abl + 48) ^ axm; } \
    uint32_t bxm = (uint32_t)((tid & 7) << 4); \
    uint32_t bbl = (uint32_t)(tid * 128);

#define PREF_S(it, buf) do { \
    _Pragma("unroll") for (int j = 0; j < 4; ++j) \
        cpa16(aBase + (buf) * ASTG_S + aoffs[j], rAp + (it) * 128 + ah * 64 + j * 16, pa0); \
    _Pragma("unroll") for (int j = 0; j < 8; ++j) \
        cpa16(bBase + (buf) * BSTG + ((bbl + j * 16) ^ bxm), rBp + (it) * 128 + j * 16, true); \
} while (0)

// ================= L config: 128 x 128, 256 thr, warps 4x2 =================
#define G16_PROLOG_L \
    __shared__ __align__(128) uint8_t As[2][ASTG_L]; \
    __shared__ __align__(128) uint8_t Bs[2][BSTG]; \
    int tid = threadIdx.x; int lane = tid & 31; int wid = tid >> 5; \
    int wm = (wid & 3) * 32, wn = (wid >> 2) * 64; \
    int g = lane >> 2, tg = lane & 3; \
    float acc[2][8][4] = {}; \
    uint32_t aBase = (uint32_t)__cvta_generic_to_shared(&As[0][0]); \
    uint32_t bBase = (uint32_t)__cvta_generic_to_shared(&Bs[0][0]); \
    int ar = tid >> 1, ah = tid & 1; \
    uint32_t aoffs[4]; \
    { uint32_t abl = (uint32_t)(ar * 128 + ah * 64); uint32_t axm = (uint32_t)((ar & 7) << 4); \
      aoffs[0] = (abl) ^ axm; aoffs[1] = (abl + 16) ^ axm; \
      aoffs[2] = (abl + 32) ^ axm; aoffs[3] = (abl + 48) ^ axm; }

#define PREF_L(it, buf) do { \
    _Pragma("unroll") for (int j = 0; j < 4; ++j) \
        cpa16(aBase + (buf) * ASTG_L + aoffs[j], rAp + (it) * 128 + ah * 64 + j * 16, pa0); \
    _Pragma("unroll") for (int j = 0; j < 4; ++j) \
        cpa16(bBase + (buf) * BSTG + aoffs[j],   rBp + (it) * 128 + ah * 64 + j * 16, true); \
} while (0)

// Compute one K=64 stage: 4 x (2 A-LDSM + 4 B-LDSM + 16 MMA) per warp.
#define COMPUTE64(buf, ASTG) do { \
    uint32_t aS = aBase + (buf) * (ASTG); \
    uint32_t bS = bBase + (buf) * BSTG; \
    _Pragma("unroll") for (int kk = 0; kk < 4; ++kk) { \
        uint32_t afr[2][4]; \
        _Pragma("unroll") for (int mi = 0; mi < 2; ++mi) { \
            int row = wm + mi * 16 + (lane & 15); \
            uint32_t lo = (uint32_t)(row * 128 + (2 * kk + (lane >> 4)) * 16); \
            LDSM4(afr[mi][0], afr[mi][1], afr[mi][2], afr[mi][3], \
                  aS + (lo ^ (uint32_t)((row & 7) << 4))); \
        } \
        uint32_t bfr[8][2]; \
        _Pragma("unroll") for (int j = 0; j < 4; ++j) { \
            int row = wn + j * 16 + ((lane & 7) | ((lane >> 4) << 3)); \
            uint32_t lo = (uint32_t)(row * 128 + (2 * kk + ((lane >> 3) & 1)) * 16); \
            uint32_t t0, t1, t2, t3; \
            LDSM4(t0, t1, t2, t3, bS + (lo ^ (uint32_t)((row & 7) << 4))); \
            bfr[2*j][0] = t0; bfr[2*j][1] = t1; \
            bfr[2*j+1][0] = t2; bfr[2*j+1][1] = t3; \
        } \
        _Pragma("unroll") for (int mi = 0; mi < 2; ++mi) \
        _Pragma("unroll") for (int ni = 0; ni < 8; ++ni) \
            mma16(acc[mi][ni], afr[mi], bfr[ni]); \
    } \
} while (0)

#define MAINLOOP_S(KIT) \
    PREF_S(0, 0); CP_COMMIT; \
    for (int it = 0; it < (KIT); ++it) { \
        int nxt = it + 1; \
        if (nxt < (KIT)) { PREF_S(nxt, nxt & 1); } \
        CP_COMMIT; \
        CP_WAIT1; __syncthreads(); \
        COMPUTE64(it & 1, ASTG_S); \
        __syncthreads(); \
    }

#define MAINLOOP_L(KIT) \
    PREF_L(0, 0); CP_COMMIT; \
    for (int it = 0; it < (KIT); ++it) { \
        int nxt = it + 1; \
        if (nxt < (KIT)) { PREF_L(nxt, nxt & 1); } \
        CP_COMMIT; \
        CP_WAIT1; __syncthreads(); \
        COMPUTE64(it & 1, ASTG_L); \
        __syncthreads(); \
    }

// ---------------------------------------------------------------------------
// Prep megakernel: Wa cvtT | Xb cvtT+colmean | W2 cvtT | W1 cvtT | z cvt | group
// ---------------------------------------------------------------------------
#define NB_WA 8192
#define NB_XB 4096
#define NB_W2 256
#define NB_W1 32
#define NB_Z  256
#define NB_PREP (NB_WA + NB_XB + NB_W2 + NB_W1 + NB_Z + 1)

__device__ __forceinline__ void cvt_tile(
    const float* __restrict__ in, __half* __restrict__ out, int R, int C,
    int r0, int c0, size_t base, float (*s)[65]) {
    int tid = threadIdx.x;
    int lr = tid >> 4, lc = (tid & 15) * 4;
    const float* src = in + base + (size_t)(r0 + lr) * C + c0 + lc;
#pragma unroll
    for (int j = 0; j < 4; ++j) {
        float4 v = *(const float4*)(src + (size_t)(j * 16) * C);
        s[lr + j * 16][lc] = v.x; s[lr + j * 16][lc + 1] = v.y;
        s[lr + j * 16][lc + 2] = v.z; s[lr + j * 16][lc + 3] = v.w;
    }
    __syncthreads();
    int rq = (tid & 15) * 4, cc = tid >> 4;
#pragma unroll
    for (int j = 0; j < 4; ++j) {
        int c_ = cc + j * 16;
        __half2 a = __floats2half2_rn(s[rq][c_], s[rq + 1][c_]);
        __half2 b = __floats2half2_rn(s[rq + 2][c_], s[rq + 3][c_]);
        uint2 u;
        u.x = *(uint32_t*)&a; u.y = *(uint32_t*)&b;
        *(uint2*)(out + base + (size_t)(c0 + c_) * R + r0 + rq) = u;
    }
}

__global__ __launch_bounds__(256) void k_prep(
    const float* __restrict__ z, const int* __restrict__ cls,
    const float* __restrict__ W1, const float* __restrict__ W2,
    const float* __restrict__ Wa, const float* __restrict__ Xb) {
    __shared__ float s[64][65];
    __shared__ float red[256];
    int b = blockIdx.x;
    int tid = threadIdx.x;
    if (b < NB_WA) {
        int bx = b & 63, by = (b >> 6) & 15, bz = b >> 10;
        cvt_tile(Wa, g_WaT, HID, NMAXX, by * 64, bx * 64,
                 (size_t)bz * HID * NMAXX, s);
        return;
    }
    b -= NB_WA;
    if (b < NB_XB) {
        int bx = b & 7, by = (b >> 3) & 63, bz = b >> 9;
        int r0 = by * 64, c0 = bx * 64;
        cvt_tile(Xb, g_XbT, NMAXX, DD, r0, c0, (size_t)bz * NMAXX * DD, s);
        int col = tid & 63, part = tid >> 6;
        float sm = 0.f;
        for (int r = part; r < 64; r += 4) sm += s[r][col];
        red[tid] = sm;
        __syncthreads();
        if (part == 0) {
            float tot = ((red[col] + red[col + 64]) + (red[col + 128] + red[col + 192]));
            g_cmpart[(bz * 64 + by) * DD + c0 + col] = tot;
        }
        return;
    }
    b -= NB_XB;
    if (b < NB_W2) {
        int bx = b & 15, by = b >> 4;
        cvt_tile(W2, g_W2T, HID, HID, by * 64, bx * 64, 0, s);
        return;
    }
    b -= NB_W2;
    if (b < NB_W1) {
        int bx = b & 15, by = b >> 4;
        cvt_tile(W1, g_W1T, LATENT, HID, by * 64, bx * 64, 0, s);
        return;
    }
    b -= NB_W1;
    if (b < NB_Z) {
        int idx = b * 256 + tid;
        float4 v = *(const float4*)(z + (size_t)idx * 4);
        __half2 a = __floats2half2_rn(v.x, v.y);
        __half2 bb = __floats2half2_rn(v.z, v.w);
        uint2 u;
        u.x = *(uint32_t*)&a; u.y = *(uint32_t*)&bb;
        *(uint2*)(g_z16 + (size_t)idx * 4) = u;
        return;
    }
    int* icnt = (int*)red;
    int* ioff = (int*)red + 16;
    if (tid < CCLS) icnt[tid] = 0;
    __syncthreads();
    for (int i = tid; i < BSZ; i += 256) atomicAdd(&icnt[cls[i]], 1);
    __syncthreads();
    if (tid == 0) {
        int sum = 0;
        for (int c = 0; c < CCLS; c++) { ioff[c] = sum; sum += icnt[c]; }
        ioff[CCLS] = sum;
        for (int c = 0; c <= CCLS; c++) g_class_off[c] = ioff[c];
    }
    __syncthreads();
    if (tid < CCLS) icnt[tid] = ioff[tid];
    __syncthreads();
    for (int i = tid; i < BSZ; i += 256) {
        int c = cls[i];
        int slot = atomicAdd(&icnt[c], 1);
        g_order[slot] = i;
    }
}

__global__ __launch_bounds__(256) void k_cm_reduce() {
    int c = blockIdx.x;
    int d = blockIdx.y * 256 + threadIdx.x;
    float s = 0.f;
#pragma unroll 8
    for (int t = 0; t < 64; ++t) s += g_cmpart[(c * 64 + t) * DD + d];
    g_colmean[c * DD + d] = s / (float)c_counts[c];
}

// ---------------------------------------------------------------------------
// Kernel 1: h = gelu(z @ W1[:128] + W1[128+cid] + b1)  -> g_h16
// ---------------------------------------------------------------------------
__global__ __launch_bounds__(NTG, 4) void k_gemm_h(
    const int* __restrict__ cls,
    const float* __restrict__ W1, const float* __restrict__ b1) {
    int m0 = blockIdx.y * 64, n0 = blockIdx.x * 128;
    G16_PROLOG_S
    bool pa0 = true;
    const char* rAp = (const char*)(g_z16 + (size_t)(m0 + ar) * LATENT);
    const char* rBp = (const char*)(g_W1T + (size_t)(n0 + tid) * LATENT);
    MAINLOOP_S(LATENT / 64)
#pragma unroll
    for (int mi = 0; mi < 2; ++mi)
#pragma unroll
    for (int r2 = 0; r2 < 2; ++r2) {
        int m = m0 + wm + mi * 16 + g + r2 * 8;
        int cid = cls[m];
        const float* wrow = W1 + (size_t)(LATENT + cid) * HID;
#pragma unroll
        for (int ni = 0; ni < 8; ++ni) {
            int n = n0 + wn + ni * 8 + tg * 2;
            float ox = gelu_exact(acc[mi][ni][r2 * 2 + 0] + wrow[n] + b1[n]);
            float oy = gelu_exact(acc[mi][ni][r2 * 2 + 1] + wrow[n + 1] + b1[n + 1]);
            *(__half2*)(g_h16 + (size_t)m * HID + n) = __floats2half2_rn(ox, oy);
        }
    }
}

// ---------------------------------------------------------------------------
// Kernel 2: gemm_t split-K=4
// ---------------------------------------------------------------------------
__global__ __launch_bounds__(NTG, 4) void k_gemm_t() {
    int m0 = blockIdx.y * 64, n0 = blockIdx.x * 128;
    int sp = blockIdx.z;
    G16_PROLOG_S
    bool pa0 = true;
    const char* rAp = (const char*)(g_h16 + (size_t)(m0 + ar) * HID + sp * (HID / 4));
    const char* rBp = (const char*)(g_W2T + (size_t)(n0 + tid) * HID + sp * (HID / 4));
    MAINLOOP_S(HID / 4 / 64)
    float* dst = g_part[sp];
#pragma unroll
    for (int mi = 0; mi < 2; ++mi)
#pragma unroll
    for (int r2 = 0; r2 < 2; ++r2) {
        int m = m0 + wm + mi * 16 + g + r2 * 8;
#pragma unroll
        for (int ni = 0; ni < 8; ++ni) {
            int n = n0 + wn + ni * 8 + tg * 2;
            float2 o;
            o.x = acc[mi][ni][r2 * 2 + 0];
            o.y = acc[mi][ni][r2 * 2 + 1];
            *(float2*)(dst + (size_t)m * HID + n) = o;
        }
    }
}

// t = gelu(p0+p1+p2+p3+b2) -> g_t16
__global__ __launch_bounds__(NT) void k_t_epi(const float* __restrict__ b2) {
    int idx = blockIdx.x * NT + threadIdx.x;
    int n = (idx & (HID / 4 - 1)) * 4;
    float4 p0 = *(const float4*)(g_part[0] + (size_t)idx * 4);
    float4 p1 = *(const float4*)(g_part[1] + (size_t)idx * 4);
    float4 p2 = *(const float4*)(g_part[2] + (size_t)idx * 4);
    float4 p3 = *(const float4*)(g_part[3] + (size_t)idx * 4);
    float4 bb = *(const float4*)(b2 + n);
    float ox = gelu_exact(((p0.x + p1.x) + (p2.x + p3.x)) + bb.x);
    float oy = gelu_exact(((p0.y + p1.y) + (p2.y + p3.y)) + bb.y);
    float oz = gelu_exact(((p0.z + p1.z) + (p2.z + p3.z)) + bb.z);
    float ow = gelu_exact(((p0.w + p1.w) + (p2.w + p3.w)) + bb.w);
    __half2 a = __floats2half2_rn(ox, oy);
    __half2 b = __floats2half2_rn(oz, ow);
    uint2 u;
    u.x = *(uint32_t*)&a; u.y = *(uint32_t*)&b;
    *(uint2*)(g_t16 + (size_t)idx * 4) = u;
}

// ---------------------------------------------------------------------------
// Kernel 3: logits split-K=2 (fp16, ldmatrix); ba added on sp==0.
// ---------------------------------------------------------------------------
__global__ __launch_bounds__(NT, 2) void k_logits(const float* __restrict__ ba) {
    int zc = blockIdx.z;
    int c = zc >> 1, sp = zc & 1;
    int off = g_class_off[c];
    int Bc = g_class_off[c + 1] - off;
    int mt = blockIdx.y, nt = blockIdx.x;
    if (mt * 128 >= Bc) return;
    int cnt = c_counts[c];
    if (nt * 128 >= cnt) return;
    int m0 = mt * 128, n0 = nt * 128;
    G16_PROLOG_L
    bool pa0 = (m0 + ar) < Bc;
    const char* rAp = (const char*)(
        (pa0 ? g_t16 + (size_t)g_order[off + m0 + ar] * HID : g_t16) + sp * (HID / 2));
    const char* rBp = (const char*)(
        g_WaT + ((size_t)c * NMAXX + n0 + ar) * HID + sp * (HID / 2));
    MAINLOOP_L(HID / 2 / 64)
    __half* dst = g_lpart16[sp];
    const float* baC = ba + (size_t)c * NMAXX;
#pragma unroll
    for (int mi = 0; mi < 2; ++mi)
#pragma unroll
    for (int r2 = 0; r2 < 2; ++r2) {
        int ml = m0 + wm + mi * 16 + g + r2 * 8;
        if (ml < Bc) {
            size_t row = (size_t)(off + ml) * NMAXX;
#pragma unroll
            for (int ni = 0; ni < 8; ++ni) {
                int n = n0 + wn + ni * 8 + tg * 2;
                float2 bb = make_float2(0.f, 0.f);
                if (sp == 0) bb = *(const float2*)(baC + n);
                *(__half2*)(dst + row + n) =
                    __floats2half2_rn(acc[mi][ni][r2 * 2 + 0] + bb.x,
                                      acc[mi][ni][r2 * 2 + 1] + bb.y);
            }
        }
    }
}

// ---------------------------------------------------------------------------
// Kernel 4: softmax fused with split-K merge.
// ---------------------------------------------------------------------------
__global__ __launch_bounds__(NT) void k_softmax() {
    __shared__ float buf[NMAXX];
    __shared__ float reds[NT];
    int r = blockIdx.x;
    int c = 0;
#pragma unroll
    for (int i = 1; i < CCLS; i++)
        if (r >= g_class_off[i]) c = i;
    int cnt = c_counts[c];
    const __half* p0 = g_lpart16[0] + (size_t)r * NMAXX;
    const __half* p1 = g_lpart16[1] + (size_t)r * NMAXX;
    __half* row16 = g_beta16 + (size_t)r * NMAXX;
    int tid = threadIdx.x;

    float s = 0.f;
    for (int i = tid * 4; i < cnt; i += NT * 4) {
        uint2 ua = *(const uint2*)(p0 + i);
        uint2 ub = *(const uint2*)(p1 + i);
        float2 a0 = __half22float2(*(__half2*)&ua.x);
        float2 a1 = __half22float2(*(__half2*)&ua.y);
        float2 b0 = __half22float2(*(__half2*)&ub.x);
        float2 b1 = __half22float2(*(__half2*)&ub.y);
        float4 v;
        v.x = exp_poly(a0.x + b0.x);
        v.y = exp_poly(a0.y + b0.y);
        v.z = exp_poly(a1.x + b1.x);
        v.w = exp_poly(a1.y + b1.y);
        s += v.x + v.y + v.z + v.w;
        *(float4*)(buf + i) = v;
    }
    reds[tid] = s;
    __syncthreads();
    for (int st = NT / 2; st > 0; st >>= 1) {
        if (tid < st) reds[tid] += reds[tid + st];
        __syncthreads();
    }
    float inv = 1.0f / reds[0];
    float invc = 1.0f / (float)cnt;

    for (int i = tid * 4; i < cnt; i += NT * 4) {
        float4 v = *(const float4*)(buf + i);
        __half2 a = __floats2half2_rn(fmaf(v.x, inv, -invc) * 256.0f,
                                      fmaf(v.y, inv, -invc) * 256.0f);
        __half2 b = __floats2half2_rn(fmaf(v.z, inv, -invc) * 256.0f,
                                      fmaf(v.w, inv, -invc) * 256.0f);
        uint2 u;
        u.x = *(uint32_t*)&a; u.y = *(uint32_t*)&b;
        *(uint2*)(row16 + i) = u;
    }
}

// ---------------------------------------------------------------------------
// Kernel 5: k_out split-K=4 (fp16, ldmatrix)
// ---------------------------------------------------------------------------
__global__ __launch_bounds__(NTG, 4) void k_out() {
    int zc = blockIdx.z;
    int c = zc >> 2, sp = zc & 3;
    int off = g_class_off[c];
    int Bc = g_class_off[c + 1] - off;
    int mt = blockIdx.y, nt = blockIdx.x;
    if (mt * 64 >= Bc) return;
    int cnt = c_counts[c];
    int koff = sp * (cnt >> 2);
    int m0 = mt * 64, n0 = nt * 128;
    G16_PROLOG_S
    bool pa0 = (m0 + ar) < Bc;
    const char* rAp = (const char*)(
        (pa0 ? g_beta16 + (size_t)(off + m0 + ar) * NMAXX : g_beta16) + koff);
    const char* rBp = (const char*)(
        g_XbT + ((size_t)c * DD + n0 + tid) * NMAXX + koff);
    int kit = cnt >> 8;   // (cnt/4)/64
    MAINLOOP_S(kit)
    float* dst = g_opart[sp];
#pragma unroll
    for (int mi = 0; mi < 2; ++mi)
#pragma unroll
    for (int r2 = 0; r2 < 2; ++r2) {
        int ml = m0 + wm + mi * 16 + g + r2 * 8;
        if (ml < Bc) {
            size_t row = (size_t)(off + ml) * DD;
#pragma unroll
            for (int ni = 0; ni < 8; ++ni) {
                int n = n0 + wn + ni * 8 + tg * 2;
                float2 o;
                o.x = acc[mi][ni][r2 * 2 + 0];
                o.y = acc[mi][ni][r2 * 2 + 1];
                *(float2*)(dst + row + n) = o;
            }
        }
    }
}

__global__ __launch_bounds__(NT) void k_out_epi(float* __restrict__ out) {
    int idx = blockIdx.x * NT + threadIdx.x;
    int r = idx >> 7;
    int n = (idx & 127) * 4;
    int c = 0;
#pragma unroll
    for (int i = 1; i < CCLS; i++)
        if (r >= g_class_off[i]) c = i;
    int b = g_order[r];
    size_t o4 = (size_t)r * DD + n;
    float4 p0 = *(const float4*)(g_opart[0] + o4);
    float4 p1 = *(const float4*)(g_opart[1] + o4);
    float4 p2 = *(const float4*)(g_opart[2] + o4);
    float4 p3 = *(const float4*)(g_opart[3] + o4);
    float4 cm = *(const float4*)(g_colmean + c * DD + n);
    const float is = 1.0f / 256.0f;
    float4 o;
    o.x = fmaf(((p0.x + p1.x) + (p2.x + p3.x)), is, cm.x);
    o.y = fmaf(((p0.y + p1.y) + (p2.y + p3.y)), is, cm.y);
    o.z = fmaf(((p0.z + p1.z) + (p2.z + p3.z)), is, cm.z);
    o.w = fmaf(((p0.w + p1.w) + (p2.w + p3.w)), is, cm.w);
    *(float4*)(out + (size_t)b * DD + n) = o;
}

// ---------------------------------------------------------------------------
extern "C" void kernel_launch(void* const* d_in, const int* in_sizes, int n_in,
                              void* d_out, int out_size) {
    const float* z   = (const float*)d_in[0];
    const int*   cls = (const int*)d_in[1];
    const float* W1  = (const float*)d_in[2];
    const float* b1  = (const float*)d_in[3];
    const float* W2  = (const float*)d_in[4];
    const float* b2  = (const float*)d_in[5];
    const float* Wa  = (const float*)d_in[6];
    const float* ba  = (const float*)d_in[7];
    const float* Xb  = (const float*)d_in[8];
    float* out = (float*)d_out;

    k_prep<<<NB_PREP, 256>>>(z, cls, W1, W2, Wa, Xb);
    k_cm_reduce<<<dim3(CCLS, DD / 256), 256>>>();
    k_gemm_h<<<dim3(HID / 128, BSZ / 64), NTG>>>(cls, W1, b1);
    k_gemm_t<<<dim3(HID / 128, BSZ / 64, 4), NTG>>>();
    k_t_epi<<<BSZ * HID / 4 / NT, NT>>>(b2);
    k_logits<<<dim3(NMAXX / 128, BSZ / 128, CCLS * 2), NT>>>(ba);
    k_softmax<<<BSZ, NT>>>();
    k_out<<<dim3(DD / 128, BSZ / 64, CCLS * 4), NTG>>>();
    k_out_epi<<<BSZ * DD / 4 / NT, NT>>>(out);
}

// round 17
// speedup vs baseline: 1.1506x; 1.1506x over previous
#include <cuda_runtime.h>
#include <cuda_fp16.h>
#include <math.h>
#include <stdint.h>

#define BSZ    2048
#define LATENT 128
#define CCLS   8
#define HID    1024
#define DD     512
#define NMAXX  4096
#define NTG    128
#define NT     256

__constant__ int c_counts[CCLS] = {1024, 1536, 2048, 2560, 3072, 3584, 3840, 4096};

// fp16 operand buffers
__device__ __align__(16) __half g_z16[BSZ * LATENT];
__device__ __align__(16) __half g_W1T[HID * LATENT];          // [n][k]
__device__ __align__(16) __half g_h16[BSZ * HID];
__device__ __align__(16) __half g_W2T[HID * HID];             // [n][k]
__device__ __align__(16) __half g_t16[BSZ * HID];
__device__ __align__(16) __half g_WaT[(size_t)CCLS * NMAXX * HID];   // [c][n][k]
__device__ __align__(16) __half g_beta16[(size_t)BSZ * NMAXX];       // beta * 256
__device__ __align__(16) __half g_XbT[(size_t)CCLS * DD * NMAXX];    // [c][d][n]
__device__ __align__(16) __half g_lpart16[2][(size_t)BSZ * NMAXX];
// fp32 partials / reductions
__device__ __align__(16) float g_part[4][BSZ * HID];
__device__ __align__(16) float g_opart[4][BSZ * DD];
__device__ __align__(16) float g_cmpart[CCLS * 64 * DD];
__device__ __align__(16) float g_colmean[CCLS * DD];
__device__ int g_order[BSZ];
__device__ int g_class_off[CCLS + 1];

__device__ __forceinline__ float gelu_exact(float x) {
    return 0.5f * x * (1.0f + erff(x * 0.70710678118654752f));
}

__device__ __forceinline__ float exp_poly(float x) {
    float p = fmaf(x, 1.984126984e-4f, 1.388888889e-3f);
    p = fmaf(x, p, 8.333333333e-3f);
    p = fmaf(x, p, 4.166666667e-2f);
    p = fmaf(x, p, 1.666666667e-1f);
    p = fmaf(x, p, 0.5f);
    p = fmaf(x, p, 1.0f);
    p = fmaf(x, p, 1.0f);
    return p;
}

__device__ __forceinline__ void mma16(float* d, const uint32_t* a, const uint32_t* b) {
    asm volatile(
        "mma.sync.aligned.m16n8k16.row.col.f32.f16.f16.f32 "
        "{%0,%1,%2,%3},{%4,%5,%6,%7},{%8,%9},{%0,%1,%2,%3};\n"
        : "+f"(d[0]), "+f"(d[1]), "+f"(d[2]), "+f"(d[3])
        : "r"(a[0]), "r"(a[1]), "r"(a[2]), "r"(a[3]), "r"(b[0]), "r"(b[1]));
}

#define LDSM4(r0, r1, r2, r3, addr) \
    asm volatile("ldmatrix.sync.aligned.m8n8.x4.shared.b16 {%0,%1,%2,%3}, [%4];" \
        : "=r"(r0), "=r"(r1), "=r"(r2), "=r"(r3) : "r"(addr))

__device__ __forceinline__ void cpa16(uint32_t dst, const void* src, bool pred) {
    int sz = pred ? 16 : 0;
    asm volatile("cp.async.cg.shared.global [%0], [%1], 16, %2;\n"
                 :: "r"(dst), "l"(src), "r"(sz));
}
#define CP_COMMIT asm volatile("cp.async.commit_group;\n")
#define CP_WAIT4  asm volatile("cp.async.wait_group 4;\n")

// Rows padded to 48 B (12 words). LDSM-phase conflict-free (proven R14/R15).
#define STAGES 6
#define RST    12
#define ASz_S  (64 * RST)
#define ASz_L  (128 * RST)
#define BSz    (128 * RST)

#define G16_PROLOG_S \
    __shared__ uint32_t As[STAGES][ASz_S]; \
    __shared__ uint32_t Bs[STAGES][BSz]; \
    int tid = threadIdx.x; int lane = tid & 31; int wid = tid >> 5; \
    int wm = (wid & 1) * 32, wn = (wid >> 1) * 64; \
    int g = lane >> 2, tg = lane & 3; \
    float acc[2][8][4] = {}; \
    uint32_t aBase = (uint32_t)__cvta_generic_to_shared(&As[0][0]); \
    uint32_t bBase = (uint32_t)__cvta_generic_to_shared(&Bs[0][0]); \
    int ar = tid >> 1, ah = tid & 1; \
    int aoff = (wm + (lane & 15)) * 48 + ((lane >> 4) << 4); \
    int boff = (wn + ((lane & 7) | ((lane >> 4) << 3))) * 48 + (((lane >> 3) & 1) << 4);

#define G16_PROLOG_L \
    __shared__ uint32_t As[STAGES][ASz_L]; \
    __shared__ uint32_t Bs[STAGES][BSz]; \
    int tid = threadIdx.x; int lane = tid & 31; int wid = tid >> 5; \
    int wm = (wid & 3) * 32, wn = (wid >> 2) * 64; \
    int g = lane >> 2, tg = lane & 3; \
    float acc[2][8][4] = {}; \
    uint32_t aBase = (uint32_t)__cvta_generic_to_shared(&As[0][0]); \
    uint32_t bBase = (uint32_t)__cvta_generic_to_shared(&Bs[0][0]); \
    int ar = tid >> 1, ah = tid & 1; \
    int aoff = (wm + (lane & 15)) * 48 + ((lane >> 4) << 4); \
    int boff = (wn + ((lane & 7) | ((lane >> 4) << 3))) * 48 + (((lane >> 3) & 1) << 4);

#define PREF16_S(it, buf) do { \
    cpa16(aBase + (uint32_t)((buf)*ASz_S + ar*RST)*4 + ah*16, rAp + (it)*32 + ah*16, pa0); \
    cpa16(bBase + (uint32_t)((buf)*BSz + tid*RST)*4,        rBp + (it)*32, true); \
    cpa16(bBase + (uint32_t)((buf)*BSz + tid*RST)*4 + 16,   rBp + (it)*32 + 16, true); \
} while (0)

#define PREF16_L(it, buf) do { \
    cpa16(aBase + (uint32_t)((buf)*ASz_L + ar*RST)*4 + ah*16, rAp + (it)*32 + ah*16, pa0); \
    cpa16(bBase + (uint32_t)((buf)*BSz + ar*RST)*4 + ah*16,   rBp + (it)*32 + ah*16, true); \
} while (0)

// ldmatrix-based compute: 6 LDSM + 16 MMA per warp K-16 step.
#define COMPUTE16(cur, ASZ) do { \
    uint32_t abp = aBase + (uint32_t)((cur) * (ASZ)) * 4 + aoff; \
    uint32_t bbp = bBase + (uint32_t)((cur) * BSz) * 4 + boff; \
    uint32_t afr[2][4]; \
    LDSM4(afr[0][0], afr[0][1], afr[0][2], afr[0][3], abp); \
    LDSM4(afr[1][0], afr[1][1], afr[1][2], afr[1][3], abp + 768); \
    uint32_t bfr[8][2]; \
    _Pragma("unroll") for (int j = 0; j < 4; ++j) { \
        uint32_t t0, t1, t2, t3; \
        LDSM4(t0, t1, t2, t3, bbp + j * 768); \
        bfr[2*j][0] = t0; bfr[2*j][1] = t1; \
        bfr[2*j+1][0] = t2; bfr[2*j+1][1] = t3; \
    } \
    _Pragma("unroll") for (int mi = 0; mi < 2; ++mi) \
    _Pragma("unroll") for (int ni = 0; ni < 8; ++ni) \
        mma16(acc[mi][ni], afr[mi], bfr[ni]); \
} while (0)

// 6-stage pipeline, prefetch distance 5, one sync per iter.
#define MAINLOOP16_S(KITERS) \
    PREF16_S(0, 0); CP_COMMIT; \
    PREF16_S(1, 1); CP_COMMIT; \
    PREF16_S(2, 2); CP_COMMIT; \
    PREF16_S(3, 3); CP_COMMIT; \
    PREF16_S(4, 4); CP_COMMIT; \
    { int cur = 0, nxb = 5; \
    for (int it = 0; it < (KITERS); ++it) { \
        CP_WAIT4; \
        __syncthreads(); \
        int nx = it + STAGES - 1; \
        if (nx < (KITERS)) { PREF16_S(nx, nxb); } \
        CP_COMMIT; \
        COMPUTE16(cur, ASz_S); \
        if (++cur == STAGES) cur = 0; \
        if (++nxb == STAGES) nxb = 0; \
    } }

#define MAINLOOP16_L(KITERS) \
    PREF16_L(0, 0); CP_COMMIT; \
    PREF16_L(1, 1); CP_COMMIT; \
    PREF16_L(2, 2); CP_COMMIT; \
    PREF16_L(3, 3); CP_COMMIT; \
    PREF16_L(4, 4); CP_COMMIT; \
    { int cur = 0, nxb = 5; \
    for (int it = 0; it < (KITERS); ++it) { \
        CP_WAIT4; \
        __syncthreads(); \
        int nx = it + STAGES - 1; \
        if (nx < (KITERS)) { PREF16_L(nx, nxb); } \
        CP_COMMIT; \
        COMPUTE16(cur, ASz_L); \
        if (++cur == STAGES) cur = 0; \
        if (++nxb == STAGES) nxb = 0; \
    } }

// ---------------------------------------------------------------------------
// Prep megakernel: Wa cvtT | Xb cvtT+colmean | W2 cvtT | W1 cvtT | z cvt | group
// ---------------------------------------------------------------------------
#define NB_WA 8192
#define NB_XB 4096
#define NB_W2 256
#define NB_W1 32
#define NB_Z  256
#define NB_PREP (NB_WA + NB_XB + NB_W2 + NB_W1 + NB_Z + 1)

__device__ __forceinline__ void cvt_tile(
    const float* __restrict__ in, __half* __restrict__ out, int R, int C,
    int r0, int c0, size_t base, float (*s)[65]) {
    int tid = threadIdx.x;
    int lr = tid >> 4, lc = (tid & 15) * 4;
    const float* src = in + base + (size_t)(r0 + lr) * C + c0 + lc;
#pragma unroll
    for (int j = 0; j < 4; ++j) {
        float4 v = *(const float4*)(src + (size_t)(j * 16) * C);
        s[lr + j * 16][lc] = v.x; s[lr + j * 16][lc + 1] = v.y;
        s[lr + j * 16][lc + 2] = v.z; s[lr + j * 16][lc + 3] = v.w;
    }
    __syncthreads();
    int rq = (tid & 15) * 4, cc = tid >> 4;
#pragma unroll
    for (int j = 0; j < 4; ++j) {
        int c_ = cc + j * 16;
        __half2 a = __floats2half2_rn(s[rq][c_], s[rq + 1][c_]);
        __half2 b = __floats2half2_rn(s[rq + 2][c_], s[rq + 3][c_]);
        uint2 u;
        u.x = *(uint32_t*)&a; u.y = *(uint32_t*)&b;
        *(uint2*)(out + base + (size_t)(c0 + c_) * R + r0 + rq) = u;
    }
}

__global__ __launch_bounds__(256) void k_prep(
    const float* __restrict__ z, const int* __restrict__ cls,
    const float* __restrict__ W1, const float* __restrict__ W2,
    const float* __restrict__ Wa, const float* __restrict__ Xb) {
    __shared__ float s[64][65];
    __shared__ float red[256];
    int b = blockIdx.x;
    int tid = threadIdx.x;
    if (b < NB_WA) {
        int bx = b & 63, by = (b >> 6) & 15, bz = b >> 10;
        cvt_tile(Wa, g_WaT, HID, NMAXX, by * 64, bx * 64,
                 (size_t)bz * HID * NMAXX, s);
        return;
    }
    b -= NB_WA;
    if (b < NB_XB) {
        int bx = b & 7, by = (b >> 3) & 63, bz = b >> 9;
        int r0 = by * 64, c0 = bx * 64;
        cvt_tile(Xb, g_XbT, NMAXX, DD, r0, c0, (size_t)bz * NMAXX * DD, s);
        int col = tid & 63, part = tid >> 6;
        float sm = 0.f;
        for (int r = part; r < 64; r += 4) sm += s[r][col];
        red[tid] = sm;
        __syncthreads();
        if (part == 0) {
            float tot = ((red[col] + red[col + 64]) + (red[col + 128] + red[col + 192]));
            g_cmpart[(bz * 64 + by) * DD + c0 + col] = tot;
        }
        return;
    }
    b -= NB_XB;
    if (b < NB_W2) {
        int bx = b & 15, by = b >> 4;
        cvt_tile(W2, g_W2T, HID, HID, by * 64, bx * 64, 0, s);
        return;
    }
    b -= NB_W2;
    if (b < NB_W1) {
        int bx = b & 15, by = b >> 4;
        cvt_tile(W1, g_W1T, LATENT, HID, by * 64, bx * 64, 0, s);
        return;
    }
    b -= NB_W1;
    if (b < NB_Z) {
        int idx = b * 256 + tid;
        float4 v = *(const float4*)(z + (size_t)idx * 4);
        __half2 a = __floats2half2_rn(v.x, v.y);
        __half2 bb = __floats2half2_rn(v.z, v.w);
        uint2 u;
        u.x = *(uint32_t*)&a; u.y = *(uint32_t*)&bb;
        *(uint2*)(g_z16 + (size_t)idx * 4) = u;
        return;
    }
    int* icnt = (int*)red;
    int* ioff = (int*)red + 16;
    if (tid < CCLS) icnt[tid] = 0;
    __syncthreads();
    for (int i = tid; i < BSZ; i += 256) atomicAdd(&icnt[cls[i]], 1);
    __syncthreads();
    if (tid == 0) {
        int sum = 0;
        for (int c = 0; c < CCLS; c++) { ioff[c] = sum; sum += icnt[c]; }
        ioff[CCLS] = sum;
        for (int c = 0; c <= CCLS; c++) g_class_off[c] = ioff[c];
    }
    __syncthreads();
    if (tid < CCLS) icnt[tid] = ioff[tid];
    __syncthreads();
    for (int i = tid; i < BSZ; i += 256) {
        int c = cls[i];
        int slot = atomicAdd(&icnt[c], 1);
        g_order[slot] = i;
    }
}

__global__ __launch_bounds__(256) void k_cm_reduce() {
    int c = blockIdx.x;
    int d = blockIdx.y * 256 + threadIdx.x;
    float s = 0.f;
#pragma unroll 8
    for (int t = 0; t < 64; ++t) s += g_cmpart[(c * 64 + t) * DD + d];
    g_colmean[c * DD + d] = s / (float)c_counts[c];
}

// ---------------------------------------------------------------------------
// Kernel 1: h = gelu(z @ W1[:128] + W1[128+cid] + b1)  -> g_h16  (S config)
// ---------------------------------------------------------------------------
__global__ __launch_bounds__(NTG, 4) void k_gemm_h(
    const int* __restrict__ cls,
    const float* __restrict__ W1, const float* __restrict__ b1) {
    int m0 = blockIdx.y * 64, n0 = blockIdx.x * 128;
    G16_PROLOG_S
    bool pa0 = true;
    const char* rAp = (const char*)(g_z16 + (size_t)(m0 + ar) * LATENT);
    const char* rBp = (const char*)(g_W1T + (size_t)(n0 + tid) * LATENT);
    MAINLOOP16_S(LATENT / 16)
#pragma unroll
    for (int mi = 0; mi < 2; ++mi)
#pragma unroll
    for (int r2 = 0; r2 < 2; ++r2) {
        int m = m0 + wm + mi * 16 + g + r2 * 8;
        int cid = cls[m];
        const float* wrow = W1 + (size_t)(LATENT + cid) * HID;
#pragma unroll
        for (int ni = 0; ni < 8; ++ni) {
            int n = n0 + wn + ni * 8 + tg * 2;
            float ox = gelu_exact(acc[mi][ni][r2 * 2 + 0] + wrow[n] + b1[n]);
            float oy = gelu_exact(acc[mi][ni][r2 * 2 + 1] + wrow[n + 1] + b1[n + 1]);
            *(__half2*)(g_h16 + (size_t)m * HID + n) = __floats2half2_rn(ox, oy);
        }
    }
}

// ---------------------------------------------------------------------------
// Kernel 2: gemm_t split-K=4, 128x128 tiles (L config) — halves L2 traffic
// ---------------------------------------------------------------------------
__global__ __launch_bounds__(NT, 2) void k_gemm_t() {
    int m0 = blockIdx.y * 128, n0 = blockIdx.x * 128;
    int sp = blockIdx.z;
    G16_PROLOG_L
    bool pa0 = true;
    const char* rAp = (const char*)(g_h16 + (size_t)(m0 + ar) * HID + sp * (HID / 4));
    const char* rBp = (const char*)(g_W2T + (size_t)(n0 + ar) * HID + sp * (HID / 4));
    MAINLOOP16_L(HID / 4 / 16)
    float* dst = g_part[sp];
#pragma unroll
    for (int mi = 0; mi < 2; ++mi)
#pragma unroll
    for (int r2 = 0; r2 < 2; ++r2) {
        int m = m0 + wm + mi * 16 + g + r2 * 8;
#pragma unroll
        for (int ni = 0; ni < 8; ++ni) {
            int n = n0 + wn + ni * 8 + tg * 2;
            float2 o;
            o.x = acc[mi][ni][r2 * 2 + 0];
            o.y = acc[mi][ni][r2 * 2 + 1];
            *(float2*)(dst + (size_t)m * HID + n) = o;
        }
    }
}

// t = gelu(p0+p1+p2+p3+b2) -> g_t16
__global__ __launch_bounds__(NT) void k_t_epi(const float* __restrict__ b2) {
    int idx = blockIdx.x * NT + threadIdx.x;
    int n = (idx & (HID / 4 - 1)) * 4;
    float4 p0 = *(const float4*)(g_part[0] + (size_t)idx * 4);
    float4 p1 = *(const float4*)(g_part[1] + (size_t)idx * 4);
    float4 p2 = *(const float4*)(g_part[2] + (size_t)idx * 4);
    float4 p3 = *(const float4*)(g_part[3] + (size_t)idx * 4);
    float4 bb = *(const float4*)(b2 + n);
    float ox = gelu_exact(((p0.x + p1.x) + (p2.x + p3.x)) + bb.x);
    float oy = gelu_exact(((p0.y + p1.y) + (p2.y + p3.y)) + bb.y);
    float oz = gelu_exact(((p0.z + p1.z) + (p2.z + p3.z)) + bb.z);
    float ow = gelu_exact(((p0.w + p1.w) + (p2.w + p3.w)) + bb.w);
    __half2 a = __floats2half2_rn(ox, oy);
    __half2 b = __floats2half2_rn(oz, ow);
    uint2 u;
    u.x = *(uint32_t*)&a; u.y = *(uint32_t*)&b;
    *(uint2*)(g_t16 + (size_t)idx * 4) = u;
}

// ---------------------------------------------------------------------------
// Kernel 3: logits split-K=2 (fp16, ldmatrix); ba added on sp==0.
// ---------------------------------------------------------------------------
__global__ __launch_bounds__(NT, 2) void k_logits(const float* __restrict__ ba) {
    int zc = blockIdx.z;
    int c = zc >> 1, sp = zc & 1;
    int off = g_class_off[c];
    int Bc = g_class_off[c + 1] - off;
    int mt = blockIdx.y, nt = blockIdx.x;
    if (mt * 128 >= Bc) return;
    int cnt = c_counts[c];
    if (nt * 128 >= cnt) return;
    int m0 = mt * 128, n0 = nt * 128;
    G16_PROLOG_L
    bool pa0 = (m0 + ar) < Bc;
    const char* rAp = (const char*)(
        (pa0 ? g_t16 + (size_t)g_order[off + m0 + ar] * HID : g_t16) + sp * (HID / 2));
    const char* rBp = (const char*)(
        g_WaT + ((size_t)c * NMAXX + n0 + ar) * HID + sp * (HID / 2));
    MAINLOOP16_L(HID / 2 / 16)
    __half* dst = g_lpart16[sp];
    const float* baC = ba + (size_t)c * NMAXX;
#pragma unroll
    for (int mi = 0; mi < 2; ++mi)
#pragma unroll
    for (int r2 = 0; r2 < 2; ++r2) {
        int ml = m0 + wm + mi * 16 + g + r2 * 8;
        if (ml < Bc) {
            size_t row = (size_t)(off + ml) * NMAXX;
#pragma unroll
            for (int ni = 0; ni < 8; ++ni) {
                int n = n0 + wn + ni * 8 + tg * 2;
                float2 bb = make_float2(0.f, 0.f);
                if (sp == 0) bb = *(const float2*)(baC + n);
                *(__half2*)(dst + row + n) =
                    __floats2half2_rn(acc[mi][ni][r2 * 2 + 0] + bb.x,
                                      acc[mi][ni][r2 * 2 + 1] + bb.y);
            }
        }
    }
}

// ---------------------------------------------------------------------------
// Kernel 4: softmax fused with split-K merge.
// ---------------------------------------------------------------------------
__global__ __launch_bounds__(NT) void k_softmax() {
    __shared__ float buf[NMAXX];
    __shared__ float reds[NT];
    int r = blockIdx.x;
    int c = 0;
#pragma unroll
    for (int i = 1; i < CCLS; i++)
        if (r >= g_class_off[i]) c = i;
    int cnt = c_counts[c];
    const __half* p0 = g_lpart16[0] + (size_t)r * NMAXX;
    const __half* p1 = g_lpart16[1] + (size_t)r * NMAXX;
    __half* row16 = g_beta16 + (size_t)r * NMAXX;
    int tid = threadIdx.x;

    float s = 0.f;
    for (int i = tid * 4; i < cnt; i += NT * 4) {
        uint2 ua = *(const uint2*)(p0 + i);
        uint2 ub = *(const uint2*)(p1 + i);
        float2 a0 = __half22float2(*(__half2*)&ua.x);
        float2 a1 = __half22float2(*(__half2*)&ua.y);
        float2 b0 = __half22float2(*(__half2*)&ub.x);
        float2 b1 = __half22float2(*(__half2*)&ub.y);
        float4 v;
        v.x = exp_poly(a0.x + b0.x);
        v.y = exp_poly(a0.y + b0.y);
        v.z = exp_poly(a1.x + b1.x);
        v.w = exp_poly(a1.y + b1.y);
        s += v.x + v.y + v.z + v.w;
        *(float4*)(buf + i) = v;
    }
    reds[tid] = s;
    __syncthreads();
    for (int st = NT / 2; st > 0; st >>= 1) {
        if (tid < st) reds[tid] += reds[tid + st];
        __syncthreads();
    }
    float inv = 1.0f / reds[0];
    float invc = 1.0f / (float)cnt;

    for (int i = tid * 4; i < cnt; i += NT * 4) {
        float4 v = *(const float4*)(buf + i);
        __half2 a = __floats2half2_rn(fmaf(v.x, inv, -invc) * 256.0f,
                                      fmaf(v.y, inv, -invc) * 256.0f);
        __half2 b = __floats2half2_rn(fmaf(v.z, inv, -invc) * 256.0f,
                                      fmaf(v.w, inv, -invc) * 256.0f);
        uint2 u;
        u.x = *(uint32_t*)&a; u.y = *(uint32_t*)&b;
        *(uint2*)(row16 + i) = u;
    }
}

// ---------------------------------------------------------------------------
// Kernel 5: k_out split-K=4, 128-row M-tiles (L config) — fewer Xb re-reads
// ---------------------------------------------------------------------------
__global__ __launch_bounds__(NT, 2) void k_out() {
    int zc = blockIdx.z;
    int c = zc >> 2, sp = zc & 3;
    int off = g_class_off[c];
    int Bc = g_class_off[c + 1] - off;
    int mt = blockIdx.y, nt = blockIdx.x;
    if (mt * 128 >= Bc) return;
    int cnt = c_counts[c];
    int koff = sp * (cnt >> 2);
    int m0 = mt * 128, n0 = nt * 128;
    G16_PROLOG_L
    bool pa0 = (m0 + ar) < Bc;
    const char* rAp = (const char*)(
        (pa0 ? g_beta16 + (size_t)(off + m0 + ar) * NMAXX : g_beta16) + koff);
    const char* rBp = (const char*)(
        g_XbT + ((size_t)c * DD + n0 + ar) * NMAXX + koff);
    int kit = cnt >> 6;   // (cnt/4)/16
    MAINLOOP16_L(kit)
    float* dst = g_opart[sp];
#pragma unroll
    for (int mi = 0; mi < 2; ++mi)
#pragma unroll
    for (int r2 = 0; r2 < 2; ++r2) {
        int ml = m0 + wm + mi * 16 + g + r2 * 8;
        if (ml < Bc) {
            size_t row = (size_t)(off + ml) * DD;
#pragma unroll
            for (int ni = 0; ni < 8; ++ni) {
                int n = n0 + wn + ni * 8 + tg * 2;
                float2 o;
                o.x = acc[mi][ni][r2 * 2 + 0];
                o.y = acc[mi][ni][r2 * 2 + 1];
                *(float2*)(dst + row + n) = o;
            }
        }
    }
}

__global__ __launch_bounds__(NT) void k_out_epi(float* __restrict__ out) {
    int idx = blockIdx.x * NT + threadIdx.x;
    int r = idx >> 7;
    int n = (idx & 127) * 4;
    int c = 0;
#pragma unroll
    for (int i = 1; i < CCLS; i++)
        if (r >= g_class_off[i]) c = i;
    int b = g_order[r];
    size_t o4 = (size_t)r * DD + n;
    float4 p0 = *(const float4*)(g_opart[0] + o4);
    float4 p1 = *(const float4*)(g_opart[1] + o4);
    float4 p2 = *(const float4*)(g_opart[2] + o4);
    float4 p3 = *(const float4*)(g_opart[3] + o4);
    float4 cm = *(const float4*)(g_colmean + c * DD + n);
    const float is = 1.0f / 256.0f;
    float4 o;
    o.x = fmaf(((p0.x + p1.x) + (p2.x + p3.x)), is, cm.x);
    o.y = fmaf(((p0.y + p1.y) + (p2.y + p3.y)), is, cm.y);
    o.z = fmaf(((p0.z + p1.z) + (p2.z + p3.z)), is, cm.z);
    o.w = fmaf(((p0.w + p1.w) + (p2.w + p3.w)), is, cm.w);
    *(float4*)(out + (size_t)b * DD + n) = o;
}

// ---------------------------------------------------------------------------
extern "C" void kernel_launch(void* const* d_in, const int* in_sizes, int n_in,
                              void* d_out, int out_size) {
    const float* z   = (const float*)d_in[0];
    const int*   cls = (const int*)d_in[1];
    const float* W1  = (const float*)d_in[2];
    const float* b1  = (const float*)d_in[3];
    const float* W2  = (const float*)d_in[4];
    const float* b2  = (const float*)d_in[5];
    const float* Wa  = (const float*)d_in[6];
    const float* ba  = (const float*)d_in[7];
    const float* Xb  = (const float*)d_in[8];
    float* out = (float*)d_out;

    k_prep<<<NB_PREP, 256>>>(z, cls, W1, W2, Wa, Xb);
    k_cm_reduce<<<dim3(CCLS, DD / 256), 256>>>();
    k_gemm_h<<<dim3(HID / 128, BSZ / 64), NTG>>>(cls, W1, b1);
    k_gemm_t<<<dim3(HID / 128, BSZ / 128, 4), NT>>>();
    k_t_epi<<<BSZ * HID / 4 / NT, NT>>>(b2);
    k_logits<<<dim3(NMAXX / 128, BSZ / 128, CCLS * 2), NT>>>(ba);
    k_softmax<<<BSZ, NT>>>();
    k_out<<<dim3(DD / 128, BSZ / 128, CCLS * 4), NT>>>();
    k_out_epi<<<BSZ * DD / 4 / NT, NT>>>(out);
}